// round 8
// baseline (speedup 1.0000x reference)
#include <cuda_runtime.h>
#include <math.h>
#include <stdint.h>

// ---------------- problem constants ----------------
constexpr int BATCH = 4;
constexpr int C = 256;
constexpr int H = 64, W = 64;
constexpr int P = H * W;              // 4096
constexpr int NH = 8, HD = 32;
constexpr int P2 = (H / 2) * (W / 2); // 1024
constexpr float SCALE = 0.1767766952966369f; // 32^-0.5
constexpr float EPS_GN = 1e-6f;
constexpr float EPS_LN = 1e-5f;

// ---------------- scratch (device globals) ----------
// stats slots: 0 = x (stage1), 1 = gridx raw (stage2), 2 = pm (stage4)
__device__ float g_stats[3][2 * BATCH];
__device__ float g_xn[BATCH * C * P];     // global_x scratch
__device__ float g_qkv[BATCH * 3 * C * P];
__device__ float g_gridx[BATCH * C * P];  // x + win_attn out (RAW, pre-GN)
__device__ float g_m[BATCH * 4 * C * P2];
__device__ float g_pm[BATCH * C * P2];
__device__ float g_qg[BATCH * C * P];
__device__ float g_kv[BATCH * 2 * C * P2];

// ---------------- mma helpers ----------------
__device__ __forceinline__ uint32_t f2tf(float f) {
    uint32_t u;
    asm("cvt.rna.tf32.f32 %0, %1;" : "=r"(u) : "f"(f));
    return u;
}
__device__ __forceinline__ void mma_tf32(float* c, const uint32_t* a,
                                         uint32_t b0, uint32_t b1) {
    asm volatile(
        "mma.sync.aligned.m16n8k8.row.col.f32.tf32.tf32.f32 "
        "{%0,%1,%2,%3}, {%4,%5,%6,%7}, {%8,%9}, {%0,%1,%2,%3};"
        : "+f"(c[0]), "+f"(c[1]), "+f"(c[2]), "+f"(c[3])
        : "r"(a[0]), "r"(a[1]), "r"(a[2]), "r"(a[3]), "r"(b0), "r"(b1));
}

// ---------------- GroupNorm helpers ----------------
__global__ void zero_stats_kernel() {
    if (threadIdx.x < 3 * 2 * BATCH) ((float*)g_stats)[threadIdx.x] = 0.f;
}

__global__ void gn_stats_kernel(const float* __restrict__ x, int per_batch, int slot) {
    int b = blockIdx.y;
    const float* xb = x + (size_t)b * per_batch;
    float s = 0.f, ss = 0.f;
    for (int i = blockIdx.x * blockDim.x + threadIdx.x; i < per_batch;
         i += gridDim.x * blockDim.x) {
        float v = xb[i];
        s += v;
        ss = fmaf(v, v, ss);
    }
#pragma unroll
    for (int o = 16; o > 0; o >>= 1) {
        s += __shfl_xor_sync(~0u, s, o);
        ss += __shfl_xor_sync(~0u, ss, o);
    }
    __shared__ float red[2][8];
    int lane = threadIdx.x & 31, wp = threadIdx.x >> 5;
    if (lane == 0) { red[0][wp] = s; red[1][wp] = ss; }
    __syncthreads();
    if (threadIdx.x < 32) {
        float a = threadIdx.x < 8 ? red[0][threadIdx.x] : 0.f;
        float q = threadIdx.x < 8 ? red[1][threadIdx.x] : 0.f;
#pragma unroll
        for (int o = 4; o > 0; o >>= 1) {
            a += __shfl_xor_sync(~0u, a, o);
            q += __shfl_xor_sync(~0u, q, o);
        }
        if (threadIdx.x == 0) {
            atomicAdd(&g_stats[slot][2 * b], a);
            atomicAdd(&g_stats[slot][2 * b + 1], q);
        }
    }
}

// ---------------- TF32 GEMM templated on BM (128 or 64) --------------------
// C[b] = A[M,K] * GN(B[b])[K,N] (+bias[M]); fused GN on B, fused stats on C.
constexpr int BLDS = 136;
template <int BM>
__global__ __launch_bounds__(256, 2)
void gemm_tf32_kernel(const float* __restrict__ A,
                      const float* __restrict__ Bm,
                      const float* __restrict__ bias,
                      float* __restrict__ Cm,
                      int M, int N, int K,
                      const float* __restrict__ gnw,
                      const float* __restrict__ gnb,
                      int slot,
                      int stats_out) {
    constexpr int ALD = (BM == 128) ? 136 : 72;
    constexpr int MT = BM / 32;          // m16 tiles per warp (4 or 2)
    constexpr int APASS = BM / 64;       // A loader passes (2 or 1)
    const int b = blockIdx.z;
    Bm += (size_t)b * K * N;
    Cm += (size_t)b * M * N;
    __shared__ uint32_t As[16 * ALD];
    __shared__ uint32_t Bs[16 * BLDS];
    const int tid = threadIdx.x;
    const int warp = tid >> 5, lane = tid & 31;
    const int wm = warp >> 2, wn = warp & 3;
    const int g = lane >> 2, tq = lane & 3;
    const int m0 = blockIdx.y * BM, n0 = blockIdx.x * 128;
    const int ar = tid >> 2;
    const int ac = (tid & 3) << 2;
    const int br = tid >> 5;
    const int bc = lane << 2;

    float mean = 0.f, inv = 0.f;
    if (gnw) {
        float cnt = (float)K * (float)N;
        mean = g_stats[slot][2 * b] / cnt;
        float var = g_stats[slot][2 * b + 1] / cnt - mean * mean;
        inv = rsqrtf(var + EPS_GN);
    }

    const float* Ap[APASS];
#pragma unroll
    for (int p = 0; p < APASS; ++p)
        Ap[p] = &A[(size_t)(m0 + ar + p * 64) * K + ac];
    const float* Bplo = &Bm[(size_t)br * N + n0 + bc];
    const float* Bphi = &Bm[(size_t)(br + 8) * N + n0 + bc];

    float4 av[APASS];
#pragma unroll
    for (int p = 0; p < APASS; ++p) av[p] = *(const float4*)Ap[p];
    float4 b0v = *(const float4*)Bplo;
    float4 b1v = *(const float4*)Bphi;

    float acc[MT][4][4] = {};
    const int ntile = K >> 4;
#pragma unroll 1
    for (int i = 0; i < ntile; ++i) {
        __syncthreads();
#pragma unroll
        for (int p = 0; p < APASS; ++p) {
            As[(ac + 0) * ALD + ar + p * 64] = f2tf(av[p].x);
            As[(ac + 1) * ALD + ar + p * 64] = f2tf(av[p].y);
            As[(ac + 2) * ALD + ar + p * 64] = f2tf(av[p].z);
            As[(ac + 3) * ALD + ar + p * 64] = f2tf(av[p].w);
        }
        if (gnw) {
            int k0r = i * 16 + br;
            float al0 = inv * gnw[k0r], be0 = gnb[k0r] - mean * al0;
            float al1 = inv * gnw[k0r + 8], be1 = gnb[k0r + 8] - mean * al1;
            uint4 bu0 = {f2tf(fmaf(b0v.x, al0, be0)), f2tf(fmaf(b0v.y, al0, be0)),
                         f2tf(fmaf(b0v.z, al0, be0)), f2tf(fmaf(b0v.w, al0, be0))};
            uint4 bu1 = {f2tf(fmaf(b1v.x, al1, be1)), f2tf(fmaf(b1v.y, al1, be1)),
                         f2tf(fmaf(b1v.z, al1, be1)), f2tf(fmaf(b1v.w, al1, be1))};
            *(uint4*)&Bs[br * BLDS + bc] = bu0;
            *(uint4*)&Bs[(br + 8) * BLDS + bc] = bu1;
        } else {
            uint4 bu0 = {f2tf(b0v.x), f2tf(b0v.y), f2tf(b0v.z), f2tf(b0v.w)};
            uint4 bu1 = {f2tf(b1v.x), f2tf(b1v.y), f2tf(b1v.z), f2tf(b1v.w)};
            *(uint4*)&Bs[br * BLDS + bc] = bu0;
            *(uint4*)&Bs[(br + 8) * BLDS + bc] = bu1;
        }
        __syncthreads();
        if (i + 1 < ntile) {
            const int k1 = (i + 1) << 4;
#pragma unroll
            for (int p = 0; p < APASS; ++p) av[p] = *(const float4*)(Ap[p] + k1);
            b0v = *(const float4*)(Bplo + (size_t)k1 * N);
            b1v = *(const float4*)(Bphi + (size_t)k1 * N);
        }
#pragma unroll
        for (int ks = 0; ks < 2; ++ks) {
            const int kb = ks * 8;
            uint32_t af[MT][4];
            uint32_t bf[4][2];
#pragma unroll
            for (int mt = 0; mt < MT; ++mt) {
                const int mb = wm * (BM / 2) + mt * 16;
                af[mt][0] = As[(kb + tq) * ALD + mb + g];
                af[mt][1] = As[(kb + tq) * ALD + mb + 8 + g];
                af[mt][2] = As[(kb + tq + 4) * ALD + mb + g];
                af[mt][3] = As[(kb + tq + 4) * ALD + mb + 8 + g];
            }
#pragma unroll
            for (int nt = 0; nt < 4; ++nt) {
                const int nb = wn * 32 + nt * 8;
                bf[nt][0] = Bs[(kb + tq) * BLDS + nb + g];
                bf[nt][1] = Bs[(kb + tq + 4) * BLDS + nb + g];
            }
#pragma unroll
            for (int mt = 0; mt < MT; ++mt)
#pragma unroll
                for (int nt = 0; nt < 4; ++nt)
                    mma_tf32(acc[mt][nt], af[mt], bf[nt][0], bf[nt][1]);
        }
    }
    float s = 0.f, ssq = 0.f;
#pragma unroll
    for (int mt = 0; mt < MT; ++mt) {
#pragma unroll
        for (int nt = 0; nt < 4; ++nt) {
            int row = m0 + wm * (BM / 2) + mt * 16 + g;
            int col = n0 + wn * 32 + nt * 8 + tq * 2;
            float bv0 = bias ? bias[row] : 0.f;
            float bv1 = bias ? bias[row + 8] : 0.f;
            float2 o0 = {acc[mt][nt][0] + bv0, acc[mt][nt][1] + bv0};
            float2 o1 = {acc[mt][nt][2] + bv1, acc[mt][nt][3] + bv1};
            *(float2*)&Cm[(size_t)row * N + col] = o0;
            *(float2*)&Cm[(size_t)(row + 8) * N + col] = o1;
            if (stats_out >= 0) {
                s += o0.x + o0.y + o1.x + o1.y;
                ssq = fmaf(o0.x, o0.x, ssq);
                ssq = fmaf(o0.y, o0.y, ssq);
                ssq = fmaf(o1.x, o1.x, ssq);
                ssq = fmaf(o1.y, o1.y, ssq);
            }
        }
    }
    if (stats_out >= 0) {
#pragma unroll
        for (int o = 16; o > 0; o >>= 1) {
            s += __shfl_xor_sync(~0u, s, o);
            ssq += __shfl_xor_sync(~0u, ssq, o);
        }
        __shared__ float red[2][8];
        if (lane == 0) { red[0][warp] = s; red[1][warp] = ssq; }
        __syncthreads();
        if (tid < 32) {
            float a = tid < 8 ? red[0][tid] : 0.f;
            float q = tid < 8 ? red[1][tid] : 0.f;
#pragma unroll
            for (int o = 4; o > 0; o >>= 1) {
                a += __shfl_xor_sync(~0u, a, o);
                q += __shfl_xor_sync(~0u, q, o);
            }
            if (tid == 0) {
                atomicAdd(&g_stats[stats_out][2 * b], a);
                atomicAdd(&g_stats[stats_out][2 * b + 1], q);
            }
        }
    }
}

// ---------------- windowed 8x8 attention via TF32 mma (lean smem) ----------
// sP (64 rows) aliases over sQ (Q is fragment-resident after extraction).
constexpr int WK_LD = 72;
constexpr int WIN_SMEM = (128 * WK_LD) * 4;   // 36.9 KB
__global__ __launch_bounds__(128, 5)
void win_attn_mma_kernel(const float* __restrict__ qkv,
                         const float* __restrict__ x,
                         float* __restrict__ out) {
    extern __shared__ uint32_t smu[];
    uint32_t* sP = smu;                  // [64][72] probs; aliases sQ
    uint32_t* sQ = smu;                  // [32][72] tf32, [d][token]
    uint32_t* sK = smu + 64 * WK_LD;     // [32][72]
    uint32_t* sV = sK + 32 * WK_LD;      // [32][72]
    float* sO = (float*)sP;              // epilogue alias

    const int win = blockIdx.x;
    const int gi = win >> 3, gj = win & 7;
    const int h = blockIdx.y;
    const int b = blockIdx.z;
    const int tid = threadIdx.x, warp = tid >> 5, lane = tid & 31;
    const int g = lane >> 2, tq = lane & 3;

    const int row0 = gi * 8;
    const int col0 = gj * 8;
    const size_t qkb = ((size_t)b * 768 + h * 32) * (size_t)P;

#pragma unroll
    for (int ch = 0; ch < 4; ++ch) {
        int idx = tid + ch * 128;
        int d = idx >> 4;
        int si = (idx >> 1) & 7;
        int sj4 = (idx & 1) << 2;
        int tok = si * 8 + sj4;
        size_t ga = qkb + (size_t)d * P + (row0 + si) * W + col0 + sj4;
        float4 qv = *(const float4*)&qkv[ga];
        float4 kv4 = *(const float4*)&qkv[ga + (size_t)256 * P];
        float4 vv = *(const float4*)&qkv[ga + (size_t)512 * P];
        uint4 qu = {f2tf(qv.x * SCALE), f2tf(qv.y * SCALE),
                    f2tf(qv.z * SCALE), f2tf(qv.w * SCALE)};
        uint4 ku = {f2tf(kv4.x), f2tf(kv4.y), f2tf(kv4.z), f2tf(kv4.w)};
        uint4 vu = {f2tf(vv.x), f2tf(vv.y), f2tf(vv.z), f2tf(vv.w)};
        *(uint4*)&sQ[d * WK_LD + tok] = qu;
        *(uint4*)&sK[d * WK_LD + tok] = ku;
        *(uint4*)&sV[d * WK_LD + tok] = vu;
    }
    __syncthreads();

    const int qb = warp * 16;
    uint32_t qf[4][4];
#pragma unroll
    for (int ks = 0; ks < 4; ++ks) {
        const int kb = ks * 8;
        qf[ks][0] = sQ[(kb + tq) * WK_LD + qb + g];
        qf[ks][1] = sQ[(kb + tq) * WK_LD + qb + 8 + g];
        qf[ks][2] = sQ[(kb + tq + 4) * WK_LD + qb + g];
        qf[ks][3] = sQ[(kb + tq + 4) * WK_LD + qb + 8 + g];
    }
    __syncthreads();   // sQ dead everywhere; sP (alias) may now be written

    float S[8][4];
#pragma unroll
    for (int nt = 0; nt < 8; ++nt) {
        const int nb = nt * 8;
        S[nt][0] = S[nt][1] = S[nt][2] = S[nt][3] = 0.f;
#pragma unroll
        for (int ks = 0; ks < 4; ++ks) {
            const int kb = ks * 8;
            uint32_t b0 = sK[(kb + tq) * WK_LD + nb + g];
            uint32_t b1 = sK[(kb + tq + 4) * WK_LD + nb + g];
            mma_tf32(S[nt], qf[ks], b0, b1);
        }
    }

    float m0 = -1e30f, m1 = -1e30f;
#pragma unroll
    for (int nt = 0; nt < 8; ++nt) {
        m0 = fmaxf(m0, fmaxf(S[nt][0], S[nt][1]));
        m1 = fmaxf(m1, fmaxf(S[nt][2], S[nt][3]));
    }
    m0 = fmaxf(m0, __shfl_xor_sync(~0u, m0, 1));
    m0 = fmaxf(m0, __shfl_xor_sync(~0u, m0, 2));
    m1 = fmaxf(m1, __shfl_xor_sync(~0u, m1, 1));
    m1 = fmaxf(m1, __shfl_xor_sync(~0u, m1, 2));
    float l0 = 0.f, l1 = 0.f;
#pragma unroll
    for (int nt = 0; nt < 8; ++nt) {
        float p0 = __expf(S[nt][0] - m0);
        float p1 = __expf(S[nt][1] - m0);
        float p2 = __expf(S[nt][2] - m1);
        float p3 = __expf(S[nt][3] - m1);
        l0 += p0 + p1; l1 += p2 + p3;
        const int col = nt * 8 + tq * 2;
        sP[(qb + g) * WK_LD + col] = f2tf(p0);
        sP[(qb + g) * WK_LD + col + 1] = f2tf(p1);
        sP[(qb + 8 + g) * WK_LD + col] = f2tf(p2);
        sP[(qb + 8 + g) * WK_LD + col + 1] = f2tf(p3);
    }
    l0 += __shfl_xor_sync(~0u, l0, 1);
    l0 += __shfl_xor_sync(~0u, l0, 2);
    l1 += __shfl_xor_sync(~0u, l1, 1);
    l1 += __shfl_xor_sync(~0u, l1, 2);
    __syncwarp();

    float O[4][4] = {};
#pragma unroll
    for (int ks = 0; ks < 8; ++ks) {
        const int kb = ks * 8;
        uint32_t af[4];
        af[0] = sP[(qb + g) * WK_LD + kb + tq];
        af[1] = sP[(qb + 8 + g) * WK_LD + kb + tq];
        af[2] = sP[(qb + g) * WK_LD + kb + tq + 4];
        af[3] = sP[(qb + 8 + g) * WK_LD + kb + tq + 4];
#pragma unroll
        for (int ntd = 0; ntd < 4; ++ntd) {
            const int nb = ntd * 8;
            uint32_t b0 = sV[(nb + g) * WK_LD + kb + tq];
            uint32_t b1 = sV[(nb + g) * WK_LD + kb + tq + 4];
            mma_tf32(O[ntd], af, b0, b1);
        }
    }

    __syncthreads();
    float rl0 = 1.f / l0, rl1 = 1.f / l1;
    const int t0 = qb + g, t1 = qb + 8 + g;
#pragma unroll
    for (int ntd = 0; ntd < 4; ++ntd) {
        const int d0 = ntd * 8 + tq * 2;
        sO[d0 * WK_LD + t0] = O[ntd][0] * rl0;
        sO[(d0 + 1) * WK_LD + t0] = O[ntd][1] * rl0;
        sO[d0 * WK_LD + t1] = O[ntd][2] * rl1;
        sO[(d0 + 1) * WK_LD + t1] = O[ntd][3] * rl1;
    }
    __syncthreads();

    float s = 0.f, ss = 0.f;
#pragma unroll
    for (int ch = 0; ch < 4; ++ch) {
        int idx = tid + ch * 128;
        int d = idx >> 4;
        int si = (idx >> 1) & 7;
        int sj4 = (idx & 1) << 2;
        int tok = si * 8 + sj4;
        size_t ga = ((size_t)b * 256 + h * 32 + d) * (size_t)P
                    + (row0 + si) * W + col0 + sj4;
        float4 xv = *(const float4*)&x[ga];
        float4 ov = *(float4*)&sO[d * WK_LD + tok];
        float4 r;
        r.x = xv.x + ov.x; r.y = xv.y + ov.y;
        r.z = xv.z + ov.z; r.w = xv.w + ov.w;
        *(float4*)&out[ga] = r;
        s += r.x + r.y + r.z + r.w;
        ss = fmaf(r.x, r.x, ss);
        ss = fmaf(r.y, r.y, ss);
        ss = fmaf(r.z, r.z, ss);
        ss = fmaf(r.w, r.w, ss);
    }
#pragma unroll
    for (int o = 16; o > 0; o >>= 1) {
        s += __shfl_xor_sync(~0u, s, o);
        ss += __shfl_xor_sync(~0u, ss, o);
    }
    __shared__ float red[2][4];
    if (lane == 0) { red[0][warp] = s; red[1][warp] = ss; }
    __syncthreads();
    if (tid == 0) {
        float a = red[0][0] + red[0][1] + red[0][2] + red[0][3];
        float qq = red[1][0] + red[1][1] + red[1][2] + red[1][3];
        atomicAdd(&g_stats[1][2 * b], a);
        atomicAdd(&g_stats[1][2 * b + 1], qq);
    }
}

// ---------------- patch merge + LN (vectorized, fused GN on gridx) ---------
__global__ __launch_bounds__(256)
void patch_merge_ln_kernel(const float* __restrict__ gx,
                           const float* __restrict__ gnw,
                           const float* __restrict__ gnb,
                           const float* __restrict__ lnw,
                           const float* __restrict__ lnb,
                           float* __restrict__ m_out) {
    const int jg = blockIdx.x;
    const int i = blockIdx.y;
    const int b = blockIdx.z;
    const int c = threadIdx.x;

    float cnt = (float)(C * P);
    float mean = g_stats[1][2 * b] / cnt;
    float var = g_stats[1][2 * b + 1] / cnt - mean * mean;
    float inv = rsqrtf(var + EPS_GN);
    float al = inv * gnw[c];
    float be = gnb[c] - mean * al;

    size_t ga = ((size_t)b * 256 + c) * (size_t)P + (2 * i) * W + 8 * jg;
    float4 r0a = *(const float4*)&gx[ga];
    float4 r0b = *(const float4*)&gx[ga + 4];
    float4 r1a = *(const float4*)&gx[ga + W];
    float4 r1b = *(const float4*)&gx[ga + W + 4];
#define GN4(v) v.x = fmaf(v.x, al, be); v.y = fmaf(v.y, al, be); \
               v.z = fmaf(v.z, al, be); v.w = fmaf(v.w, al, be);
    GN4(r0a) GN4(r0b) GN4(r1a) GN4(r1b)
#undef GN4

    float v0[4] = {r0a.x, r0a.z, r0b.x, r0b.z};
    float v1[4] = {r1a.x, r1a.z, r1b.x, r1b.z};
    float v2[4] = {r0a.y, r0a.w, r0b.y, r0b.w};
    float v3[4] = {r1a.y, r1a.w, r1b.y, r1b.w};

    float s[4], ss[4];
#pragma unroll
    for (int t = 0; t < 4; ++t) {
        s[t] = v0[t] + v1[t] + v2[t] + v3[t];
        ss[t] = v0[t] * v0[t] + v1[t] * v1[t] + v2[t] * v2[t] + v3[t] * v3[t];
    }
#pragma unroll
    for (int t = 0; t < 4; ++t) {
#pragma unroll
        for (int o = 16; o > 0; o >>= 1) {
            s[t] += __shfl_xor_sync(~0u, s[t], o);
            ss[t] += __shfl_xor_sync(~0u, ss[t], o);
        }
    }
    __shared__ float red[2][8][4];
    const int lane = c & 31, wp = c >> 5;
    if (lane == 0) {
#pragma unroll
        for (int t = 0; t < 4; ++t) { red[0][wp][t] = s[t]; red[1][wp][t] = ss[t]; }
    }
    __syncthreads();
    __shared__ float smean[4], sinv[4];
    if (c < 4) {
        float a = 0.f, q = 0.f;
#pragma unroll
        for (int w8 = 0; w8 < 8; ++w8) { a += red[0][w8][c]; q += red[1][w8][c]; }
        float mu = a * (1.f / 1024.f);
        smean[c] = mu;
        sinv[c] = rsqrtf(q * (1.f / 1024.f) - mu * mu + EPS_LN);
    }
    __syncthreads();

    const size_t ob = (size_t)b * 1024 * (size_t)P2 + i * 32 + jg * 4;
#pragma unroll
    for (int q = 0; q < 4; ++q) {
        const int k = q * 256 + c;
        const float w_ = lnw[k], bb = lnb[k];
        const float* vq = (q == 0) ? v0 : (q == 1) ? v1 : (q == 2) ? v2 : v3;
        float4 o;
        o.x = (vq[0] - smean[0]) * sinv[0] * w_ + bb;
        o.y = (vq[1] - smean[1]) * sinv[1] * w_ + bb;
        o.z = (vq[2] - smean[2]) * sinv[2] * w_ + bb;
        o.w = (vq[3] - smean[3]) * sinv[3] * w_ + bb;
        *(float4*)&m_out[ob + (size_t)k * P2] = o;
    }
}

// ---------------- global attention: flash-style TF32 mma (lean smem) -------
constexpr int SQ_LD = 136;
constexpr int SK_LD = 72;
constexpr int GLOB_SMEM = (2 * 32 * SK_LD + 128 * SK_LD) * 4;
__global__ __launch_bounds__(128, 3)
void glob_attn_mma_kernel(const float* __restrict__ qg,
                          const float* __restrict__ kv,
                          const float* __restrict__ gridx,
                          const float* __restrict__ gnw,
                          const float* __restrict__ gnb,
                          float* __restrict__ out) {
    extern __shared__ uint32_t smg[];
    uint32_t* sK = smg;
    uint32_t* sV = sK + 32 * SK_LD;
    uint32_t* sP = sV + 32 * SK_LD;
    float* sQ = (float*)sP;

    const int b = blockIdx.z, h = blockIdx.y;
    const int q0 = blockIdx.x * 128;
    const int tid = threadIdx.x, warp = tid >> 5, lane = tid & 31;
    const int g = lane >> 2, tq = lane & 3;

    const size_t qbase = ((size_t)b * 256 + h * 32) * (size_t)P + q0;
    for (int i = tid; i < 32 * 32; i += 128) {
        int d = i >> 5, q4 = (i & 31) << 2;
        float4 v = *(const float4*)&qg[qbase + (size_t)d * P + q4];
        v.x *= SCALE; v.y *= SCALE; v.z *= SCALE; v.w *= SCALE;
        *(float4*)&sQ[d * SQ_LD + q4] = v;
    }
    __syncthreads();

    uint32_t qf[2][4][4];
#pragma unroll
    for (int mt = 0; mt < 2; ++mt) {
        const int qb = warp * 32 + mt * 16;
#pragma unroll
        for (int ks = 0; ks < 4; ++ks) {
            const int kb = ks * 8;
            qf[mt][ks][0] = f2tf(sQ[(kb + tq) * SQ_LD + qb + g]);
            qf[mt][ks][1] = f2tf(sQ[(kb + tq) * SQ_LD + qb + 8 + g]);
            qf[mt][ks][2] = f2tf(sQ[(kb + tq + 4) * SQ_LD + qb + g]);
            qf[mt][ks][3] = f2tf(sQ[(kb + tq + 4) * SQ_LD + qb + 8 + g]);
        }
    }

    float O[2][4][4] = {};
    float mrow[2][2], lrow[2][2];
#pragma unroll
    for (int mt = 0; mt < 2; ++mt) {
        mrow[mt][0] = mrow[mt][1] = -1e30f;
        lrow[mt][0] = lrow[mt][1] = 0.f;
    }

    const size_t kbase = ((size_t)b * 512 + h * 32) * (size_t)P2;
    const size_t vbase = kbase + (size_t)256 * P2;

    for (int t = 0; t < P2; t += 64) {
        __syncthreads();
        for (int i = tid; i < 32 * 16; i += 128) {
            int d = i >> 4, c4 = (i & 15) << 2;
            float4 kk = *(const float4*)&kv[kbase + (size_t)d * P2 + t + c4];
            float4 vv = *(const float4*)&kv[vbase + (size_t)d * P2 + t + c4];
            uint4 ku = {f2tf(kk.x), f2tf(kk.y), f2tf(kk.z), f2tf(kk.w)};
            uint4 vu = {f2tf(vv.x), f2tf(vv.y), f2tf(vv.z), f2tf(vv.w)};
            *(uint4*)&sK[d * SK_LD + c4] = ku;
            *(uint4*)&sV[d * SK_LD + c4] = vu;
        }
        __syncthreads();

        float S[2][8][4];
#pragma unroll
        for (int nt = 0; nt < 8; ++nt) {
            const int nb = nt * 8;
            uint32_t b0[4], b1[4];
#pragma unroll
            for (int ks = 0; ks < 4; ++ks) {
                const int kb = ks * 8;
                b0[ks] = sK[(kb + tq) * SK_LD + nb + g];
                b1[ks] = sK[(kb + tq + 4) * SK_LD + nb + g];
            }
#pragma unroll
            for (int mt = 0; mt < 2; ++mt) {
                S[mt][nt][0] = S[mt][nt][1] = S[mt][nt][2] = S[mt][nt][3] = 0.f;
#pragma unroll
                for (int ks = 0; ks < 4; ++ks)
                    mma_tf32(S[mt][nt], qf[mt][ks], b0[ks], b1[ks]);
            }
        }

#pragma unroll
        for (int mt = 0; mt < 2; ++mt) {
            const int qb = warp * 32 + mt * 16;
            float tm0 = -1e30f, tm1 = -1e30f;
#pragma unroll
            for (int nt = 0; nt < 8; ++nt) {
                tm0 = fmaxf(tm0, fmaxf(S[mt][nt][0], S[mt][nt][1]));
                tm1 = fmaxf(tm1, fmaxf(S[mt][nt][2], S[mt][nt][3]));
            }
            tm0 = fmaxf(tm0, __shfl_xor_sync(~0u, tm0, 1));
            tm0 = fmaxf(tm0, __shfl_xor_sync(~0u, tm0, 2));
            tm1 = fmaxf(tm1, __shfl_xor_sync(~0u, tm1, 1));
            tm1 = fmaxf(tm1, __shfl_xor_sync(~0u, tm1, 2));
            float m0n = fmaxf(mrow[mt][0], tm0);
            float m1n = fmaxf(mrow[mt][1], tm1);
            float c0 = __expf(mrow[mt][0] - m0n);
            float c1 = __expf(mrow[mt][1] - m1n);
            mrow[mt][0] = m0n; mrow[mt][1] = m1n;
            float s0 = 0.f, s1 = 0.f;
#pragma unroll
            for (int nt = 0; nt < 8; ++nt) {
                float p0 = __expf(S[mt][nt][0] - m0n);
                float p1 = __expf(S[mt][nt][1] - m0n);
                float p2 = __expf(S[mt][nt][2] - m1n);
                float p3 = __expf(S[mt][nt][3] - m1n);
                s0 += p0 + p1; s1 += p2 + p3;
                const int col = nt * 8 + tq * 2;
                sP[(qb + g) * SK_LD + col] = f2tf(p0);
                sP[(qb + g) * SK_LD + col + 1] = f2tf(p1);
                sP[(qb + 8 + g) * SK_LD + col] = f2tf(p2);
                sP[(qb + 8 + g) * SK_LD + col + 1] = f2tf(p3);
            }
            s0 += __shfl_xor_sync(~0u, s0, 1);
            s0 += __shfl_xor_sync(~0u, s0, 2);
            s1 += __shfl_xor_sync(~0u, s1, 1);
            s1 += __shfl_xor_sync(~0u, s1, 2);
            lrow[mt][0] = lrow[mt][0] * c0 + s0;
            lrow[mt][1] = lrow[mt][1] * c1 + s1;
#pragma unroll
            for (int ntd = 0; ntd < 4; ++ntd) {
                O[mt][ntd][0] *= c0; O[mt][ntd][1] *= c0;
                O[mt][ntd][2] *= c1; O[mt][ntd][3] *= c1;
            }
        }
        __syncwarp();

#pragma unroll
        for (int ks = 0; ks < 8; ++ks) {
            const int kb = ks * 8;
            uint32_t af[2][4];
#pragma unroll
            for (int mt = 0; mt < 2; ++mt) {
                const int qb = warp * 32 + mt * 16;
                af[mt][0] = sP[(qb + g) * SK_LD + kb + tq];
                af[mt][1] = sP[(qb + 8 + g) * SK_LD + kb + tq];
                af[mt][2] = sP[(qb + g) * SK_LD + kb + tq + 4];
                af[mt][3] = sP[(qb + 8 + g) * SK_LD + kb + tq + 4];
            }
#pragma unroll
            for (int ntd = 0; ntd < 4; ++ntd) {
                const int nb = ntd * 8;
                uint32_t b0 = sV[(nb + g) * SK_LD + kb + tq];
                uint32_t b1 = sV[(nb + g) * SK_LD + kb + tq + 4];
#pragma unroll
                for (int mt = 0; mt < 2; ++mt)
                    mma_tf32(O[mt][ntd], af[mt], b0, b1);
            }
        }
    }

    __syncthreads();
#pragma unroll
    for (int mt = 0; mt < 2; ++mt) {
        const int qb = warp * 32 + mt * 16;
        float rl0 = 1.f / lrow[mt][0];
        float rl1 = 1.f / lrow[mt][1];
#pragma unroll
        for (int ntd = 0; ntd < 4; ++ntd) {
            const int d0 = ntd * 8 + tq * 2;
            sQ[(d0) * SQ_LD + qb + g] = O[mt][ntd][0] * rl0;
            sQ[(d0 + 1) * SQ_LD + qb + g] = O[mt][ntd][1] * rl0;
            sQ[(d0) * SQ_LD + qb + 8 + g] = O[mt][ntd][2] * rl1;
            sQ[(d0 + 1) * SQ_LD + qb + 8 + g] = O[mt][ntd][3] * rl1;
        }
    }
    __syncthreads();
    {
        float cnt = (float)(C * P);
        float mean = g_stats[1][2 * b] / cnt;
        float var = g_stats[1][2 * b + 1] / cnt - mean * mean;
        float inv = rsqrtf(var + EPS_GN);
        for (int i = tid; i < 32 * 32; i += 128) {
            int d = i >> 5, q4 = (i & 31) << 2;
            int cch = h * 32 + d;
            float al = inv * gnw[cch];
            float be = gnb[cch] - mean * al;
            float4 o = *(float4*)&sQ[d * SQ_LD + q4];
            float4 r = *(const float4*)&gridx[qbase + (size_t)d * P + q4];
            o.x += fmaf(r.x, al, be);
            o.y += fmaf(r.y, al, be);
            o.z += fmaf(r.z, al, be);
            o.w += fmaf(r.w, al, be);
            *(float4*)&out[qbase + (size_t)d * P + q4] = o;
        }
    }
}

// ---------------- host launcher ----------------
static float* sym_addr(const void* s) {
    void* p = nullptr;
    cudaGetSymbolAddress(&p, s);
    return (float*)p;
}

extern "C" void kernel_launch(void* const* d_in, const int* in_sizes, int n_in,
                              void* d_out, int out_size) {
    const float* x        = (const float*)d_in[0];
    const float* norm_w   = (const float*)d_in[1];
    const float* norm_b   = (const float*)d_in[2];
    const float* qkv_w    = (const float*)d_in[3];
    const float* qkv_b    = (const float*)d_in[4];
    const float* proj_w   = (const float*)d_in[5];
    const float* proj_b   = (const float*)d_in[6];
    const float* gridnw   = (const float*)d_in[7];
    const float* gridnb   = (const float*)d_in[8];
    const float* pm_ln_w  = (const float*)d_in[9];
    const float* pm_ln_b  = (const float*)d_in[10];
    const float* pm_red_w = (const float*)d_in[11];
    const float* ds_nw    = (const float*)d_in[12];
    const float* ds_nb    = (const float*)d_in[13];
    const float* q_w      = (const float*)d_in[14];
    const float* q_b      = (const float*)d_in[15];
    const float* kv_w     = (const float*)d_in[16];
    const float* kv_b     = (const float*)d_in[17];
    float* out = (float*)d_out;

    float* xn    = sym_addr(g_xn);
    float* qkv   = sym_addr(g_qkv);
    float* gridx = sym_addr(g_gridx);
    float* mbuf  = sym_addr(g_m);
    float* pm    = sym_addr(g_pm);
    float* qg    = sym_addr(g_qg);
    float* kvb   = sym_addr(g_kv);

    cudaFuncSetAttribute(win_attn_mma_kernel,
                         cudaFuncAttributeMaxDynamicSharedMemorySize, WIN_SMEM);
    cudaFuncSetAttribute(glob_attn_mma_kernel,
                         cudaFuncAttributeMaxDynamicSharedMemorySize, GLOB_SMEM);

    dim3 gnGrid(64, BATCH);

    zero_stats_kernel<<<1, 32>>>();

    // ---- stage 1: stats(x); qkv = conv1x1(GN(x)) (GN fused, BM=128) ----
    gn_stats_kernel<<<gnGrid, 256>>>(x, C * P, 0);
    gemm_tf32_kernel<128><<<dim3(P / 128, 768 / 128, BATCH), 256>>>(
        qkv_w, x, qkv_b, qkv, 768, P, C, norm_w, norm_b, 0, -1);

    // ---- stage 2: windowed attention + residual + fused stats(slot1) ----
    win_attn_mma_kernel<<<dim3(64, NH, BATCH), 128, WIN_SMEM>>>(qkv, x, gridx);

    // ---- stage 3: patch merge (GN fused) + LN; pm GEMM BM=64 (+stats) ----
    patch_merge_ln_kernel<<<dim3(8, 32, BATCH), 256>>>(
        gridx, gridnw, gridnb, pm_ln_w, pm_ln_b, mbuf);
    gemm_tf32_kernel<64><<<dim3(P2 / 128, C / 64, BATCH), 256>>>(
        pm_red_w, mbuf, nullptr, pm, C, P2, 4 * C, nullptr, nullptr, -1, 2);

    // ---- stage 4: q projection (GN slot1 fused, BM=64); kv (GN slot2, BM=64) ----
    gemm_tf32_kernel<64><<<dim3(P / 128, C / 64, BATCH), 256>>>(
        q_w, gridx, q_b, qg, C, P, C, gridnw, gridnb, 1, -1);
    gemm_tf32_kernel<64><<<dim3(P2 / 128, 512 / 64, BATCH), 256>>>(
        kv_w, pm, kv_b, kvb, 512, P2, C, ds_nw, ds_nb, 2, -1);

    // ---- stage 5: global attention + GN(gridx) residual ----
    glob_attn_mma_kernel<<<dim3(P / 128, NH, BATCH), 128, GLOB_SMEM>>>(
        qg, kvb, gridx, gridnw, gridnb, xn);

    // ---- stage 6: proj (BM=64) ----
    gemm_tf32_kernel<64><<<dim3(P / 128, C / 64, BATCH), 256>>>(
        proj_w, xn, proj_b, out, C, P, C, nullptr, nullptr, -1, -1);
}

// round 9
// speedup vs baseline: 1.0485x; 1.0485x over previous
#include <cuda_runtime.h>
#include <math.h>
#include <stdint.h>

// ---------------- problem constants ----------------
constexpr int BATCH = 4;
constexpr int C = 256;
constexpr int H = 64, W = 64;
constexpr int P = H * W;              // 4096
constexpr int NH = 8, HD = 32;
constexpr int P2 = (H / 2) * (W / 2); // 1024
constexpr float SCALE = 0.1767766952966369f; // 32^-0.5
constexpr float EPS_GN = 1e-6f;
constexpr float EPS_LN = 1e-5f;

// ---------------- scratch (device globals) ----------
// stats slots: 0 = x (stage1), 1 = gridx raw (stage2), 2 = pm (stage4)
__device__ float g_stats[3][2 * BATCH];
__device__ float g_xn[BATCH * C * P];     // global_x scratch
__device__ float g_qkv[BATCH * 3 * C * P];
__device__ float g_gridx[BATCH * C * P];  // x + win_attn out (RAW, pre-GN)
__device__ float g_m[BATCH * 4 * C * P2];
__device__ float g_pm[BATCH * C * P2];
__device__ float g_qg[BATCH * C * P];
__device__ float g_kv[BATCH * 2 * C * P2];

// ---------------- mma / async helpers ----------------
__device__ __forceinline__ uint32_t f2tf(float f) {
    uint32_t u;
    asm("cvt.rna.tf32.f32 %0, %1;" : "=r"(u) : "f"(f));
    return u;
}
__device__ __forceinline__ void mma_tf32(float* c, const uint32_t* a,
                                         uint32_t b0, uint32_t b1) {
    asm volatile(
        "mma.sync.aligned.m16n8k8.row.col.f32.tf32.tf32.f32 "
        "{%0,%1,%2,%3}, {%4,%5,%6,%7}, {%8,%9}, {%0,%1,%2,%3};"
        : "+f"(c[0]), "+f"(c[1]), "+f"(c[2]), "+f"(c[3])
        : "r"(a[0]), "r"(a[1]), "r"(a[2]), "r"(a[3]), "r"(b0), "r"(b1));
}
__device__ __forceinline__ void cp_async16(uint32_t smem_dst, const void* gsrc) {
    asm volatile("cp.async.cg.shared.global [%0], [%1], 16;"
                 :: "r"(smem_dst), "l"(gsrc));
}
__device__ __forceinline__ void cp_commit() {
    asm volatile("cp.async.commit_group;");
}
__device__ __forceinline__ void cp_wait_all() {
    asm volatile("cp.async.wait_group 0;");
}

// ---------------- GroupNorm helpers ----------------
__global__ void zero_stats_kernel() {
    if (threadIdx.x < 3 * 2 * BATCH) ((float*)g_stats)[threadIdx.x] = 0.f;
}

__global__ void gn_stats_kernel(const float* __restrict__ x, int per_batch, int slot) {
    int b = blockIdx.y;
    const float* xb = x + (size_t)b * per_batch;
    float s = 0.f, ss = 0.f;
    for (int i = blockIdx.x * blockDim.x + threadIdx.x; i < per_batch;
         i += gridDim.x * blockDim.x) {
        float v = xb[i];
        s += v;
        ss = fmaf(v, v, ss);
    }
#pragma unroll
    for (int o = 16; o > 0; o >>= 1) {
        s += __shfl_xor_sync(~0u, s, o);
        ss += __shfl_xor_sync(~0u, ss, o);
    }
    __shared__ float red[2][8];
    int lane = threadIdx.x & 31, wp = threadIdx.x >> 5;
    if (lane == 0) { red[0][wp] = s; red[1][wp] = ss; }
    __syncthreads();
    if (threadIdx.x < 32) {
        float a = threadIdx.x < 8 ? red[0][threadIdx.x] : 0.f;
        float q = threadIdx.x < 8 ? red[1][threadIdx.x] : 0.f;
#pragma unroll
        for (int o = 4; o > 0; o >>= 1) {
            a += __shfl_xor_sync(~0u, a, o);
            q += __shfl_xor_sync(~0u, q, o);
        }
        if (threadIdx.x == 0) {
            atomicAdd(&g_stats[slot][2 * b], a);
            atomicAdd(&g_stats[slot][2 * b + 1], q);
        }
    }
}

// ---------------- TF32 GEMM: cp.async 2-stage pipeline, K-tile 32 ----------
// C[b] = A[M,K] * GN(B[b])[K,N] (+bias[M]); raw-fp32 smem, truncated-tf32 mma.
// A in smem as [m][k] (LDA=36), B as [k][n] (LDB=136) — conflict-free frags.
constexpr int KT = 32;
constexpr int ALD2 = 36;
constexpr int BLD2 = 136;
template <int BM>
constexpr int gemm_smem_bytes() {
    return (2 * BM * ALD2 + 2 * KT * BLD2 + 2 * 256) * 4;
}
template <int BM>
__global__ __launch_bounds__(256, 2)
void gemm_tf32_kernel(const float* __restrict__ A,
                      const float* __restrict__ Bm,
                      const float* __restrict__ bias,
                      float* __restrict__ Cm,
                      int M, int N, int K,
                      const float* __restrict__ gnw,
                      const float* __restrict__ gnb,
                      int slot,
                      int stats_out) {
    constexpr int MT = BM / 32;          // m16 tiles per warp
    constexpr int ACHUNK = BM * 8 / 256; // 16B chunks per thread for A tile
    extern __shared__ float smem[];
    float* As[2] = {smem, smem + BM * ALD2};
    float* Bs[2] = {smem + 2 * BM * ALD2, smem + 2 * BM * ALD2 + KT * BLD2};
    float* sAl = smem + 2 * BM * ALD2 + 2 * KT * BLD2;
    float* sBe = sAl + 256;

    const int b = blockIdx.z;
    Bm += (size_t)b * K * N;
    Cm += (size_t)b * M * N;
    const int tid = threadIdx.x;
    const int warp = tid >> 5, lane = tid & 31;
    const int wm = warp >> 2, wn = warp & 3;
    const int g = lane >> 2, tq = lane & 3;
    const int m0 = blockIdx.y * BM, n0 = blockIdx.x * 128;

    if (gnw) {
        float cnt = (float)K * (float)N;
        float mean = g_stats[slot][2 * b] / cnt;
        float var = g_stats[slot][2 * b + 1] / cnt - mean * mean;
        float inv = rsqrtf(var + EPS_GN);
        for (int k = tid; k < K && k < 256; k += 256) {
            float al = inv * gnw[k];
            sAl[k] = al;
            sBe[k] = fmaf(-mean, al, gnb[k]);
        }
    }

    // loader lambdas (manual): A chunks: row = c>>3, kc = (c&7)*4
    //                          B chunks: row = c>>5, nc = (c&31)*4
    const int a_row[4] = {(tid + 0) >> 3, (tid + 256) >> 3,
                          (tid + 512) >> 3, (tid + 768) >> 3};
    const int a_kc = (tid & 7) << 2;
    const int b_row[4] = {(tid + 0) >> 5, (tid + 256) >> 5,
                          (tid + 512) >> 5, (tid + 768) >> 5};
    const int b_nc = (tid & 31) << 2;

    uint32_t asb[2], bsb[2];
#pragma unroll
    for (int st = 0; st < 2; ++st) {
        asb[st] = (uint32_t)__cvta_generic_to_shared(As[st]);
        bsb[st] = (uint32_t)__cvta_generic_to_shared(Bs[st]);
    }

    auto issue = [&](int stage, int k0) {
#pragma unroll
        for (int p = 0; p < ACHUNK; ++p) {
            int row = a_row[p];
            cp_async16(asb[stage] + (row * ALD2 + a_kc) * 4,
                       &A[(size_t)(m0 + row) * K + k0 + a_kc]);
        }
#pragma unroll
        for (int p = 0; p < 4; ++p) {
            int row = b_row[p];
            cp_async16(bsb[stage] + (row * BLD2 + b_nc) * 4,
                       &Bm[(size_t)(k0 + row) * N + n0 + b_nc]);
        }
        cp_commit();
    };

    float acc[MT][4][4] = {};
    const int ntile = K / KT;
    issue(0, 0);
#pragma unroll 1
    for (int i = 0; i < ntile; ++i) {
        const int cur = i & 1;
        cp_wait_all();
        __syncthreads();
        if (i + 1 < ntile) issue(cur ^ 1, (i + 1) * KT);
        const float* as = As[cur];
        const float* bs = Bs[cur];
#pragma unroll
        for (int ks = 0; ks < 4; ++ks) {
            const int kb = ks * 8;
            uint32_t af[MT][4];
#pragma unroll
            for (int mt = 0; mt < MT; ++mt) {
                const int mb = wm * (BM / 2) + mt * 16;
                af[mt][0] = __float_as_uint(as[(mb + g) * ALD2 + kb + tq]);
                af[mt][1] = __float_as_uint(as[(mb + 8 + g) * ALD2 + kb + tq]);
                af[mt][2] = __float_as_uint(as[(mb + g) * ALD2 + kb + tq + 4]);
                af[mt][3] = __float_as_uint(as[(mb + 8 + g) * ALD2 + kb + tq + 4]);
            }
            uint32_t bf[4][2];
            if (gnw) {
                const int kk = i * KT + kb;
                float al0 = sAl[kk + tq], be0 = sBe[kk + tq];
                float al1 = sAl[kk + tq + 4], be1 = sBe[kk + tq + 4];
#pragma unroll
                for (int nt = 0; nt < 4; ++nt) {
                    const int nb = wn * 32 + nt * 8;
                    float r0 = bs[(kb + tq) * BLD2 + nb + g];
                    float r1 = bs[(kb + tq + 4) * BLD2 + nb + g];
                    bf[nt][0] = __float_as_uint(fmaf(r0, al0, be0));
                    bf[nt][1] = __float_as_uint(fmaf(r1, al1, be1));
                }
            } else {
#pragma unroll
                for (int nt = 0; nt < 4; ++nt) {
                    const int nb = wn * 32 + nt * 8;
                    bf[nt][0] = __float_as_uint(bs[(kb + tq) * BLD2 + nb + g]);
                    bf[nt][1] = __float_as_uint(bs[(kb + tq + 4) * BLD2 + nb + g]);
                }
            }
#pragma unroll
            for (int mt = 0; mt < MT; ++mt)
#pragma unroll
                for (int nt = 0; nt < 4; ++nt)
                    mma_tf32(acc[mt][nt], af[mt], bf[nt][0], bf[nt][1]);
        }
        __syncthreads();
    }

    float s = 0.f, ssq = 0.f;
#pragma unroll
    for (int mt = 0; mt < MT; ++mt) {
#pragma unroll
        for (int nt = 0; nt < 4; ++nt) {
            int row = m0 + wm * (BM / 2) + mt * 16 + g;
            int col = n0 + wn * 32 + nt * 8 + tq * 2;
            float bv0 = bias ? bias[row] : 0.f;
            float bv1 = bias ? bias[row + 8] : 0.f;
            float2 o0 = {acc[mt][nt][0] + bv0, acc[mt][nt][1] + bv0};
            float2 o1 = {acc[mt][nt][2] + bv1, acc[mt][nt][3] + bv1};
            *(float2*)&Cm[(size_t)row * N + col] = o0;
            *(float2*)&Cm[(size_t)(row + 8) * N + col] = o1;
            if (stats_out >= 0) {
                s += o0.x + o0.y + o1.x + o1.y;
                ssq = fmaf(o0.x, o0.x, ssq);
                ssq = fmaf(o0.y, o0.y, ssq);
                ssq = fmaf(o1.x, o1.x, ssq);
                ssq = fmaf(o1.y, o1.y, ssq);
            }
        }
    }
    if (stats_out >= 0) {
#pragma unroll
        for (int o = 16; o > 0; o >>= 1) {
            s += __shfl_xor_sync(~0u, s, o);
            ssq += __shfl_xor_sync(~0u, ssq, o);
        }
        __shared__ float red[2][8];
        if (lane == 0) { red[0][warp] = s; red[1][warp] = ssq; }
        __syncthreads();
        if (tid < 32) {
            float a = tid < 8 ? red[0][tid] : 0.f;
            float q = tid < 8 ? red[1][tid] : 0.f;
#pragma unroll
            for (int o = 4; o > 0; o >>= 1) {
                a += __shfl_xor_sync(~0u, a, o);
                q += __shfl_xor_sync(~0u, q, o);
            }
            if (tid == 0) {
                atomicAdd(&g_stats[stats_out][2 * b], a);
                atomicAdd(&g_stats[stats_out][2 * b + 1], q);
            }
        }
    }
}

// ---------------- windowed 8x8 attention via TF32 mma (unchanged) ----------
constexpr int WK_LD = 72;
constexpr int WIN_SMEM = (128 * WK_LD) * 4;   // 36.9 KB
__global__ __launch_bounds__(128, 5)
void win_attn_mma_kernel(const float* __restrict__ qkv,
                         const float* __restrict__ x,
                         float* __restrict__ out) {
    extern __shared__ uint32_t smu[];
    uint32_t* sP = smu;
    uint32_t* sQ = smu;
    uint32_t* sK = smu + 64 * WK_LD;
    uint32_t* sV = sK + 32 * WK_LD;
    float* sO = (float*)sP;

    const int win = blockIdx.x;
    const int gi = win >> 3, gj = win & 7;
    const int h = blockIdx.y;
    const int b = blockIdx.z;
    const int tid = threadIdx.x, warp = tid >> 5, lane = tid & 31;
    const int g = lane >> 2, tq = lane & 3;

    const int row0 = gi * 8;
    const int col0 = gj * 8;
    const size_t qkb = ((size_t)b * 768 + h * 32) * (size_t)P;

#pragma unroll
    for (int ch = 0; ch < 4; ++ch) {
        int idx = tid + ch * 128;
        int d = idx >> 4;
        int si = (idx >> 1) & 7;
        int sj4 = (idx & 1) << 2;
        int tok = si * 8 + sj4;
        size_t ga = qkb + (size_t)d * P + (row0 + si) * W + col0 + sj4;
        float4 qv = *(const float4*)&qkv[ga];
        float4 kv4 = *(const float4*)&qkv[ga + (size_t)256 * P];
        float4 vv = *(const float4*)&qkv[ga + (size_t)512 * P];
        uint4 qu = {f2tf(qv.x * SCALE), f2tf(qv.y * SCALE),
                    f2tf(qv.z * SCALE), f2tf(qv.w * SCALE)};
        uint4 ku = {f2tf(kv4.x), f2tf(kv4.y), f2tf(kv4.z), f2tf(kv4.w)};
        uint4 vu = {f2tf(vv.x), f2tf(vv.y), f2tf(vv.z), f2tf(vv.w)};
        *(uint4*)&sQ[d * WK_LD + tok] = qu;
        *(uint4*)&sK[d * WK_LD + tok] = ku;
        *(uint4*)&sV[d * WK_LD + tok] = vu;
    }
    __syncthreads();

    const int qb = warp * 16;
    uint32_t qf[4][4];
#pragma unroll
    for (int ks = 0; ks < 4; ++ks) {
        const int kb = ks * 8;
        qf[ks][0] = sQ[(kb + tq) * WK_LD + qb + g];
        qf[ks][1] = sQ[(kb + tq) * WK_LD + qb + 8 + g];
        qf[ks][2] = sQ[(kb + tq + 4) * WK_LD + qb + g];
        qf[ks][3] = sQ[(kb + tq + 4) * WK_LD + qb + 8 + g];
    }
    __syncthreads();

    float S[8][4];
#pragma unroll
    for (int nt = 0; nt < 8; ++nt) {
        const int nb = nt * 8;
        S[nt][0] = S[nt][1] = S[nt][2] = S[nt][3] = 0.f;
#pragma unroll
        for (int ks = 0; ks < 4; ++ks) {
            const int kb = ks * 8;
            uint32_t b0 = sK[(kb + tq) * WK_LD + nb + g];
            uint32_t b1 = sK[(kb + tq + 4) * WK_LD + nb + g];
            mma_tf32(S[nt], qf[ks], b0, b1);
        }
    }

    float m0 = -1e30f, m1 = -1e30f;
#pragma unroll
    for (int nt = 0; nt < 8; ++nt) {
        m0 = fmaxf(m0, fmaxf(S[nt][0], S[nt][1]));
        m1 = fmaxf(m1, fmaxf(S[nt][2], S[nt][3]));
    }
    m0 = fmaxf(m0, __shfl_xor_sync(~0u, m0, 1));
    m0 = fmaxf(m0, __shfl_xor_sync(~0u, m0, 2));
    m1 = fmaxf(m1, __shfl_xor_sync(~0u, m1, 1));
    m1 = fmaxf(m1, __shfl_xor_sync(~0u, m1, 2));
    float l0 = 0.f, l1 = 0.f;
#pragma unroll
    for (int nt = 0; nt < 8; ++nt) {
        float p0 = __expf(S[nt][0] - m0);
        float p1 = __expf(S[nt][1] - m0);
        float p2 = __expf(S[nt][2] - m1);
        float p3 = __expf(S[nt][3] - m1);
        l0 += p0 + p1; l1 += p2 + p3;
        const int col = nt * 8 + tq * 2;
        sP[(qb + g) * WK_LD + col] = f2tf(p0);
        sP[(qb + g) * WK_LD + col + 1] = f2tf(p1);
        sP[(qb + 8 + g) * WK_LD + col] = f2tf(p2);
        sP[(qb + 8 + g) * WK_LD + col + 1] = f2tf(p3);
    }
    l0 += __shfl_xor_sync(~0u, l0, 1);
    l0 += __shfl_xor_sync(~0u, l0, 2);
    l1 += __shfl_xor_sync(~0u, l1, 1);
    l1 += __shfl_xor_sync(~0u, l1, 2);
    __syncwarp();

    float O[4][4] = {};
#pragma unroll
    for (int ks = 0; ks < 8; ++ks) {
        const int kb = ks * 8;
        uint32_t af[4];
        af[0] = sP[(qb + g) * WK_LD + kb + tq];
        af[1] = sP[(qb + 8 + g) * WK_LD + kb + tq];
        af[2] = sP[(qb + g) * WK_LD + kb + tq + 4];
        af[3] = sP[(qb + 8 + g) * WK_LD + kb + tq + 4];
#pragma unroll
        for (int ntd = 0; ntd < 4; ++ntd) {
            const int nb = ntd * 8;
            uint32_t b0 = sV[(nb + g) * WK_LD + kb + tq];
            uint32_t b1 = sV[(nb + g) * WK_LD + kb + tq + 4];
            mma_tf32(O[ntd], af, b0, b1);
        }
    }

    __syncthreads();
    float rl0 = 1.f / l0, rl1 = 1.f / l1;
    const int t0 = qb + g, t1 = qb + 8 + g;
#pragma unroll
    for (int ntd = 0; ntd < 4; ++ntd) {
        const int d0 = ntd * 8 + tq * 2;
        sO[d0 * WK_LD + t0] = O[ntd][0] * rl0;
        sO[(d0 + 1) * WK_LD + t0] = O[ntd][1] * rl0;
        sO[d0 * WK_LD + t1] = O[ntd][2] * rl1;
        sO[(d0 + 1) * WK_LD + t1] = O[ntd][3] * rl1;
    }
    __syncthreads();

    float s = 0.f, ss = 0.f;
#pragma unroll
    for (int ch = 0; ch < 4; ++ch) {
        int idx = tid + ch * 128;
        int d = idx >> 4;
        int si = (idx >> 1) & 7;
        int sj4 = (idx & 1) << 2;
        int tok = si * 8 + sj4;
        size_t ga = ((size_t)b * 256 + h * 32 + d) * (size_t)P
                    + (row0 + si) * W + col0 + sj4;
        float4 xv = *(const float4*)&x[ga];
        float4 ov = *(float4*)&sO[d * WK_LD + tok];
        float4 r;
        r.x = xv.x + ov.x; r.y = xv.y + ov.y;
        r.z = xv.z + ov.z; r.w = xv.w + ov.w;
        *(float4*)&out[ga] = r;
        s += r.x + r.y + r.z + r.w;
        ss = fmaf(r.x, r.x, ss);
        ss = fmaf(r.y, r.y, ss);
        ss = fmaf(r.z, r.z, ss);
        ss = fmaf(r.w, r.w, ss);
    }
#pragma unroll
    for (int o = 16; o > 0; o >>= 1) {
        s += __shfl_xor_sync(~0u, s, o);
        ss += __shfl_xor_sync(~0u, ss, o);
    }
    __shared__ float red[2][4];
    if (lane == 0) { red[0][warp] = s; red[1][warp] = ss; }
    __syncthreads();
    if (tid == 0) {
        float a = red[0][0] + red[0][1] + red[0][2] + red[0][3];
        float qq = red[1][0] + red[1][1] + red[1][2] + red[1][3];
        atomicAdd(&g_stats[1][2 * b], a);
        atomicAdd(&g_stats[1][2 * b + 1], qq);
    }
}

// ---------------- patch merge + LN (unchanged) ----------------
__global__ __launch_bounds__(256)
void patch_merge_ln_kernel(const float* __restrict__ gx,
                           const float* __restrict__ gnw,
                           const float* __restrict__ gnb,
                           const float* __restrict__ lnw,
                           const float* __restrict__ lnb,
                           float* __restrict__ m_out) {
    const int jg = blockIdx.x;
    const int i = blockIdx.y;
    const int b = blockIdx.z;
    const int c = threadIdx.x;

    float cnt = (float)(C * P);
    float mean = g_stats[1][2 * b] / cnt;
    float var = g_stats[1][2 * b + 1] / cnt - mean * mean;
    float inv = rsqrtf(var + EPS_GN);
    float al = inv * gnw[c];
    float be = gnb[c] - mean * al;

    size_t ga = ((size_t)b * 256 + c) * (size_t)P + (2 * i) * W + 8 * jg;
    float4 r0a = *(const float4*)&gx[ga];
    float4 r0b = *(const float4*)&gx[ga + 4];
    float4 r1a = *(const float4*)&gx[ga + W];
    float4 r1b = *(const float4*)&gx[ga + W + 4];
#define GN4(v) v.x = fmaf(v.x, al, be); v.y = fmaf(v.y, al, be); \
               v.z = fmaf(v.z, al, be); v.w = fmaf(v.w, al, be);
    GN4(r0a) GN4(r0b) GN4(r1a) GN4(r1b)
#undef GN4

    float v0[4] = {r0a.x, r0a.z, r0b.x, r0b.z};
    float v1[4] = {r1a.x, r1a.z, r1b.x, r1b.z};
    float v2[4] = {r0a.y, r0a.w, r0b.y, r0b.w};
    float v3[4] = {r1a.y, r1a.w, r1b.y, r1b.w};

    float s[4], ss[4];
#pragma unroll
    for (int t = 0; t < 4; ++t) {
        s[t] = v0[t] + v1[t] + v2[t] + v3[t];
        ss[t] = v0[t] * v0[t] + v1[t] * v1[t] + v2[t] * v2[t] + v3[t] * v3[t];
    }
#pragma unroll
    for (int t = 0; t < 4; ++t) {
#pragma unroll
        for (int o = 16; o > 0; o >>= 1) {
            s[t] += __shfl_xor_sync(~0u, s[t], o);
            ss[t] += __shfl_xor_sync(~0u, ss[t], o);
        }
    }
    __shared__ float red[2][8][4];
    const int lane = c & 31, wp = c >> 5;
    if (lane == 0) {
#pragma unroll
        for (int t = 0; t < 4; ++t) { red[0][wp][t] = s[t]; red[1][wp][t] = ss[t]; }
    }
    __syncthreads();
    __shared__ float smean[4], sinv[4];
    if (c < 4) {
        float a = 0.f, q = 0.f;
#pragma unroll
        for (int w8 = 0; w8 < 8; ++w8) { a += red[0][w8][c]; q += red[1][w8][c]; }
        float mu = a * (1.f / 1024.f);
        smean[c] = mu;
        sinv[c] = rsqrtf(q * (1.f / 1024.f) - mu * mu + EPS_LN);
    }
    __syncthreads();

    const size_t ob = (size_t)b * 1024 * (size_t)P2 + i * 32 + jg * 4;
#pragma unroll
    for (int q = 0; q < 4; ++q) {
        const int k = q * 256 + c;
        const float w_ = lnw[k], bb = lnb[k];
        const float* vq = (q == 0) ? v0 : (q == 1) ? v1 : (q == 2) ? v2 : v3;
        float4 o;
        o.x = (vq[0] - smean[0]) * sinv[0] * w_ + bb;
        o.y = (vq[1] - smean[1]) * sinv[1] * w_ + bb;
        o.z = (vq[2] - smean[2]) * sinv[2] * w_ + bb;
        o.w = (vq[3] - smean[3]) * sinv[3] * w_ + bb;
        *(float4*)&m_out[ob + (size_t)k * P2] = o;
    }
}

// ---------------- global attention: flash-style TF32 mma (unchanged) -------
constexpr int SQ_LD = 136;
constexpr int SK_LD = 72;
constexpr int GLOB_SMEM = (2 * 32 * SK_LD + 128 * SK_LD) * 4;
__global__ __launch_bounds__(128, 3)
void glob_attn_mma_kernel(const float* __restrict__ qg,
                          const float* __restrict__ kv,
                          const float* __restrict__ gridx,
                          const float* __restrict__ gnw,
                          const float* __restrict__ gnb,
                          float* __restrict__ out) {
    extern __shared__ uint32_t smg[];
    uint32_t* sK = smg;
    uint32_t* sV = sK + 32 * SK_LD;
    uint32_t* sP = sV + 32 * SK_LD;
    float* sQ = (float*)sP;

    const int b = blockIdx.z, h = blockIdx.y;
    const int q0 = blockIdx.x * 128;
    const int tid = threadIdx.x, warp = tid >> 5, lane = tid & 31;
    const int g = lane >> 2, tq = lane & 3;

    const size_t qbase = ((size_t)b * 256 + h * 32) * (size_t)P + q0;
    for (int i = tid; i < 32 * 32; i += 128) {
        int d = i >> 5, q4 = (i & 31) << 2;
        float4 v = *(const float4*)&qg[qbase + (size_t)d * P + q4];
        v.x *= SCALE; v.y *= SCALE; v.z *= SCALE; v.w *= SCALE;
        *(float4*)&sQ[d * SQ_LD + q4] = v;
    }
    __syncthreads();

    uint32_t qf[2][4][4];
#pragma unroll
    for (int mt = 0; mt < 2; ++mt) {
        const int qb = warp * 32 + mt * 16;
#pragma unroll
        for (int ks = 0; ks < 4; ++ks) {
            const int kb = ks * 8;
            qf[mt][ks][0] = f2tf(sQ[(kb + tq) * SQ_LD + qb + g]);
            qf[mt][ks][1] = f2tf(sQ[(kb + tq) * SQ_LD + qb + 8 + g]);
            qf[mt][ks][2] = f2tf(sQ[(kb + tq + 4) * SQ_LD + qb + g]);
            qf[mt][ks][3] = f2tf(sQ[(kb + tq + 4) * SQ_LD + qb + 8 + g]);
        }
    }

    float O[2][4][4] = {};
    float mrow[2][2], lrow[2][2];
#pragma unroll
    for (int mt = 0; mt < 2; ++mt) {
        mrow[mt][0] = mrow[mt][1] = -1e30f;
        lrow[mt][0] = lrow[mt][1] = 0.f;
    }

    const size_t kbase = ((size_t)b * 512 + h * 32) * (size_t)P2;
    const size_t vbase = kbase + (size_t)256 * P2;

    for (int t = 0; t < P2; t += 64) {
        __syncthreads();
        for (int i = tid; i < 32 * 16; i += 128) {
            int d = i >> 4, c4 = (i & 15) << 2;
            float4 kk = *(const float4*)&kv[kbase + (size_t)d * P2 + t + c4];
            float4 vv = *(const float4*)&kv[vbase + (size_t)d * P2 + t + c4];
            uint4 ku = {f2tf(kk.x), f2tf(kk.y), f2tf(kk.z), f2tf(kk.w)};
            uint4 vu = {f2tf(vv.x), f2tf(vv.y), f2tf(vv.z), f2tf(vv.w)};
            *(uint4*)&sK[d * SK_LD + c4] = ku;
            *(uint4*)&sV[d * SK_LD + c4] = vu;
        }
        __syncthreads();

        float S[2][8][4];
#pragma unroll
        for (int nt = 0; nt < 8; ++nt) {
            const int nb = nt * 8;
            uint32_t b0[4], b1[4];
#pragma unroll
            for (int ks = 0; ks < 4; ++ks) {
                const int kb = ks * 8;
                b0[ks] = sK[(kb + tq) * SK_LD + nb + g];
                b1[ks] = sK[(kb + tq + 4) * SK_LD + nb + g];
            }
#pragma unroll
            for (int mt = 0; mt < 2; ++mt) {
                S[mt][nt][0] = S[mt][nt][1] = S[mt][nt][2] = S[mt][nt][3] = 0.f;
#pragma unroll
                for (int ks = 0; ks < 4; ++ks)
                    mma_tf32(S[mt][nt], qf[mt][ks], b0[ks], b1[ks]);
            }
        }

#pragma unroll
        for (int mt = 0; mt < 2; ++mt) {
            const int qb = warp * 32 + mt * 16;
            float tm0 = -1e30f, tm1 = -1e30f;
#pragma unroll
            for (int nt = 0; nt < 8; ++nt) {
                tm0 = fmaxf(tm0, fmaxf(S[mt][nt][0], S[mt][nt][1]));
                tm1 = fmaxf(tm1, fmaxf(S[mt][nt][2], S[mt][nt][3]));
            }
            tm0 = fmaxf(tm0, __shfl_xor_sync(~0u, tm0, 1));
            tm0 = fmaxf(tm0, __shfl_xor_sync(~0u, tm0, 2));
            tm1 = fmaxf(tm1, __shfl_xor_sync(~0u, tm1, 1));
            tm1 = fmaxf(tm1, __shfl_xor_sync(~0u, tm1, 2));
            float m0n = fmaxf(mrow[mt][0], tm0);
            float m1n = fmaxf(mrow[mt][1], tm1);
            float c0 = __expf(mrow[mt][0] - m0n);
            float c1 = __expf(mrow[mt][1] - m1n);
            mrow[mt][0] = m0n; mrow[mt][1] = m1n;
            float s0 = 0.f, s1 = 0.f;
#pragma unroll
            for (int nt = 0; nt < 8; ++nt) {
                float p0 = __expf(S[mt][nt][0] - m0n);
                float p1 = __expf(S[mt][nt][1] - m0n);
                float p2 = __expf(S[mt][nt][2] - m1n);
                float p3 = __expf(S[mt][nt][3] - m1n);
                s0 += p0 + p1; s1 += p2 + p3;
                const int col = nt * 8 + tq * 2;
                sP[(qb + g) * SK_LD + col] = f2tf(p0);
                sP[(qb + g) * SK_LD + col + 1] = f2tf(p1);
                sP[(qb + 8 + g) * SK_LD + col] = f2tf(p2);
                sP[(qb + 8 + g) * SK_LD + col + 1] = f2tf(p3);
            }
            s0 += __shfl_xor_sync(~0u, s0, 1);
            s0 += __shfl_xor_sync(~0u, s0, 2);
            s1 += __shfl_xor_sync(~0u, s1, 1);
            s1 += __shfl_xor_sync(~0u, s1, 2);
            lrow[mt][0] = lrow[mt][0] * c0 + s0;
            lrow[mt][1] = lrow[mt][1] * c1 + s1;
#pragma unroll
            for (int ntd = 0; ntd < 4; ++ntd) {
                O[mt][ntd][0] *= c0; O[mt][ntd][1] *= c0;
                O[mt][ntd][2] *= c1; O[mt][ntd][3] *= c1;
            }
        }
        __syncwarp();

#pragma unroll
        for (int ks = 0; ks < 8; ++ks) {
            const int kb = ks * 8;
            uint32_t af[2][4];
#pragma unroll
            for (int mt = 0; mt < 2; ++mt) {
                const int qb = warp * 32 + mt * 16;
                af[mt][0] = sP[(qb + g) * SK_LD + kb + tq];
                af[mt][1] = sP[(qb + 8 + g) * SK_LD + kb + tq];
                af[mt][2] = sP[(qb + g) * SK_LD + kb + tq + 4];
                af[mt][3] = sP[(qb + 8 + g) * SK_LD + kb + tq + 4];
            }
#pragma unroll
            for (int ntd = 0; ntd < 4; ++ntd) {
                const int nb = ntd * 8;
                uint32_t b0 = sV[(nb + g) * SK_LD + kb + tq];
                uint32_t b1 = sV[(nb + g) * SK_LD + kb + tq + 4];
#pragma unroll
                for (int mt = 0; mt < 2; ++mt)
                    mma_tf32(O[mt][ntd], af[mt], b0, b1);
            }
        }
    }

    __syncthreads();
#pragma unroll
    for (int mt = 0; mt < 2; ++mt) {
        const int qb = warp * 32 + mt * 16;
        float rl0 = 1.f / lrow[mt][0];
        float rl1 = 1.f / lrow[mt][1];
#pragma unroll
        for (int ntd = 0; ntd < 4; ++ntd) {
            const int d0 = ntd * 8 + tq * 2;
            sQ[(d0) * SQ_LD + qb + g] = O[mt][ntd][0] * rl0;
            sQ[(d0 + 1) * SQ_LD + qb + g] = O[mt][ntd][1] * rl0;
            sQ[(d0) * SQ_LD + qb + 8 + g] = O[mt][ntd][2] * rl1;
            sQ[(d0 + 1) * SQ_LD + qb + 8 + g] = O[mt][ntd][3] * rl1;
        }
    }
    __syncthreads();
    {
        float cnt = (float)(C * P);
        float mean = g_stats[1][2 * b] / cnt;
        float var = g_stats[1][2 * b + 1] / cnt - mean * mean;
        float inv = rsqrtf(var + EPS_GN);
        for (int i = tid; i < 32 * 32; i += 128) {
            int d = i >> 5, q4 = (i & 31) << 2;
            int cch = h * 32 + d;
            float al = inv * gnw[cch];
            float be = gnb[cch] - mean * al;
            float4 o = *(float4*)&sQ[d * SQ_LD + q4];
            float4 r = *(const float4*)&gridx[qbase + (size_t)d * P + q4];
            o.x += fmaf(r.x, al, be);
            o.y += fmaf(r.y, al, be);
            o.z += fmaf(r.z, al, be);
            o.w += fmaf(r.w, al, be);
            *(float4*)&out[qbase + (size_t)d * P + q4] = o;
        }
    }
}

// ---------------- host launcher ----------------
static float* sym_addr(const void* s) {
    void* p = nullptr;
    cudaGetSymbolAddress(&p, s);
    return (float*)p;
}

extern "C" void kernel_launch(void* const* d_in, const int* in_sizes, int n_in,
                              void* d_out, int out_size) {
    const float* x        = (const float*)d_in[0];
    const float* norm_w   = (const float*)d_in[1];
    const float* norm_b   = (const float*)d_in[2];
    const float* qkv_w    = (const float*)d_in[3];
    const float* qkv_b    = (const float*)d_in[4];
    const float* proj_w   = (const float*)d_in[5];
    const float* proj_b   = (const float*)d_in[6];
    const float* gridnw   = (const float*)d_in[7];
    const float* gridnb   = (const float*)d_in[8];
    const float* pm_ln_w  = (const float*)d_in[9];
    const float* pm_ln_b  = (const float*)d_in[10];
    const float* pm_red_w = (const float*)d_in[11];
    const float* ds_nw    = (const float*)d_in[12];
    const float* ds_nb    = (const float*)d_in[13];
    const float* q_w      = (const float*)d_in[14];
    const float* q_b      = (const float*)d_in[15];
    const float* kv_w     = (const float*)d_in[16];
    const float* kv_b     = (const float*)d_in[17];
    float* out = (float*)d_out;

    float* xn    = sym_addr(g_xn);
    float* qkv   = sym_addr(g_qkv);
    float* gridx = sym_addr(g_gridx);
    float* mbuf  = sym_addr(g_m);
    float* pm    = sym_addr(g_pm);
    float* qg    = sym_addr(g_qg);
    float* kvb   = sym_addr(g_kv);

    constexpr int GS128 = gemm_smem_bytes<128>();
    constexpr int GS64 = gemm_smem_bytes<64>();
    cudaFuncSetAttribute(gemm_tf32_kernel<128>,
                         cudaFuncAttributeMaxDynamicSharedMemorySize, GS128);
    cudaFuncSetAttribute(gemm_tf32_kernel<64>,
                         cudaFuncAttributeMaxDynamicSharedMemorySize, GS64);
    cudaFuncSetAttribute(win_attn_mma_kernel,
                         cudaFuncAttributeMaxDynamicSharedMemorySize, WIN_SMEM);
    cudaFuncSetAttribute(glob_attn_mma_kernel,
                         cudaFuncAttributeMaxDynamicSharedMemorySize, GLOB_SMEM);

    dim3 gnGrid(64, BATCH);

    zero_stats_kernel<<<1, 32>>>();

    // ---- stage 1: stats(x); qkv = conv1x1(GN(x)) (GN fused, BM=128) ----
    gn_stats_kernel<<<gnGrid, 256>>>(x, C * P, 0);
    gemm_tf32_kernel<128><<<dim3(P / 128, 768 / 128, BATCH), 256, GS128>>>(
        qkv_w, x, qkv_b, qkv, 768, P, C, norm_w, norm_b, 0, -1);

    // ---- stage 2: windowed attention + residual + fused stats(slot1) ----
    win_attn_mma_kernel<<<dim3(64, NH, BATCH), 128, WIN_SMEM>>>(qkv, x, gridx);

    // ---- stage 3: patch merge (GN fused) + LN; pm GEMM BM=64 (+stats) ----
    patch_merge_ln_kernel<<<dim3(8, 32, BATCH), 256>>>(
        gridx, gridnw, gridnb, pm_ln_w, pm_ln_b, mbuf);
    gemm_tf32_kernel<64><<<dim3(P2 / 128, C / 64, BATCH), 256, GS64>>>(
        pm_red_w, mbuf, nullptr, pm, C, P2, 4 * C, nullptr, nullptr, -1, 2);

    // ---- stage 4: q projection (GN slot1 fused); kv (GN slot2) ----
    gemm_tf32_kernel<64><<<dim3(P / 128, C / 64, BATCH), 256, GS64>>>(
        q_w, gridx, q_b, qg, C, P, C, gridnw, gridnb, 1, -1);
    gemm_tf32_kernel<64><<<dim3(P2 / 128, 512 / 64, BATCH), 256, GS64>>>(
        kv_w, pm, kv_b, kvb, 512, P2, C, ds_nw, ds_nb, 2, -1);

    // ---- stage 5: global attention + GN(gridx) residual ----
    glob_attn_mma_kernel<<<dim3(P / 128, NH, BATCH), 128, GLOB_SMEM>>>(
        qg, kvb, gridx, gridnw, gridnb, xn);

    // ---- stage 6: proj (BM=64) ----
    gemm_tf32_kernel<64><<<dim3(P / 128, C / 64, BATCH), 256, GS64>>>(
        proj_w, xn, proj_b, out, C, P, C, nullptr, nullptr, -1, -1);
}